// round 2
// baseline (speedup 1.0000x reference)
#include <cuda_runtime.h>

// Conv2d: x[32,128,56,56] (*) K[256,128,3,3], pad 1, stride 1, + scalar bias.
// Implicit GEMM: out[k][p] = sum_e W[k][e] * im2col(x)[e][p]
//   k in [0,256)  (output channels)
//   p in [0,100352) = n*3136 + oh*56 + ow
//   e in [0,1152)  = c*9 + r*3 + s   (matches OIHW contiguous layout of K)
// Tile: 128(k) x 128(p) x 8(e), 256 threads, 8x8 register micro-tile.

#define C_IN    128
#define H_IN    56
#define W_IN    56
#define K_OUT   256
#define HW      (H_IN * W_IN)       // 3136
#define E_TOT   (C_IN * 9)          // 1152
#define P_TOT   (32 * HW)           // 100352

#define TILE_K  128
#define TILE_P  128
#define TILE_E  8

__global__ __launch_bounds__(256, 2)
void conv2d_igemm_f32(const float* __restrict__ x,
                      const float* __restrict__ w,
                      const float* __restrict__ bias,
                      float* __restrict__ out) {
    __shared__ float As[TILE_E][TILE_K];   // weights, [e_local][k_local]
    __shared__ float Bs[TILE_E][TILE_P];   // im2col input, [e_local][p_local]

    const int tid = threadIdx.x;
    const int tx  = tid & 15;    // p micro-tile index
    const int ty  = tid >> 4;    // k micro-tile index
    const int k0  = blockIdx.y * TILE_K;
    const int p0  = blockIdx.x * TILE_P;

    // ---- per-thread B-load coords (p_local = tid % 128 is the same for all 4 loads) ----
    const int pl   = tid & 127;
    const int p    = p0 + pl;
    const int bn   = p / HW;
    const int phw  = p - bn * HW;
    const int boh  = phw / W_IN;
    const int bow  = phw - boh * W_IN;
    const float* xbase = x + (long long)bn * C_IN * HW;

    // ---- A-load coords: thread loads float4 of weights ----
    const int a_krow = tid >> 1;
    const int a_ecol = (tid & 1) * 4;
    const float* wrow = w + (long long)(k0 + a_krow) * E_TOT + a_ecol;

    float acc[8][8];
    #pragma unroll
    for (int i = 0; i < 8; i++)
        #pragma unroll
        for (int j = 0; j < 8; j++)
            acc[i][j] = 0.0f;

    for (int e0 = 0; e0 < E_TOT; e0 += TILE_E) {
        // load weight tile (coalesced float4, stored transposed into smem)
        float4 wv = *reinterpret_cast<const float4*>(wrow + e0);
        As[a_ecol + 0][a_krow] = wv.x;
        As[a_ecol + 1][a_krow] = wv.y;
        As[a_ecol + 2][a_krow] = wv.z;
        As[a_ecol + 3][a_krow] = wv.w;

        // load input tile (implicit im2col, coalesced along p)
        #pragma unroll
        for (int l = 0; l < 4; l++) {
            int kk = ((tid + l * 256) >> 7);       // 0..7
            int e  = e0 + kk;
            int c  = e / 9;
            int rs = e - c * 9;
            int r  = rs / 3;
            int s  = rs - r * 3;
            int ih = boh + r - 1;
            int iw = bow + s - 1;
            float v = 0.0f;
            if ((unsigned)ih < (unsigned)H_IN && (unsigned)iw < (unsigned)W_IN)
                v = xbase[(c * H_IN + ih) * W_IN + iw];
            Bs[kk][pl] = v;
        }
        __syncthreads();

        #pragma unroll
        for (int kk = 0; kk < TILE_E; kk++) {
            float a[8], b[8];
            #pragma unroll
            for (int j = 0; j < 8; j++) a[j] = As[kk][ty * 8 + j];
            #pragma unroll
            for (int j = 0; j < 8; j++) b[j] = Bs[kk][tx * 8 + j];
            #pragma unroll
            for (int i = 0; i < 8; i++)
                #pragma unroll
                for (int j = 0; j < 8; j++)
                    acc[i][j] = fmaf(a[i], b[j], acc[i][j]);
        }
        __syncthreads();
    }

    // ---- epilogue: scalar bias + NCHW scatter (coalesced along p within an image) ----
    const float bv = bias[0];
    #pragma unroll
    for (int i = 0; i < 8; i++) {
        int k = k0 + ty * 8 + i;
        #pragma unroll
        for (int j = 0; j < 8; j++) {
            int pp = p0 + tx * 8 + j;
            int n  = pp / HW;
            int hw = pp - n * HW;
            out[((long long)n * K_OUT + k) * HW + hw] = acc[i][j] + bv;
        }
    }
}

extern "C" void kernel_launch(void* const* d_in, const int* in_sizes, int n_in,
                              void* d_out, int out_size) {
    const float* x    = (const float*)d_in[0];
    const float* K    = (const float*)d_in[1];
    const float* bias = (const float*)d_in[2];
    float* out        = (float*)d_out;

    dim3 grid(P_TOT / TILE_P, K_OUT / TILE_K);   // (784, 2)
    conv2d_igemm_f32<<<grid, 256>>>(x, K, bias, out);
}

// round 4
// speedup vs baseline: 3.4976x; 3.4976x over previous
#include <cuda_runtime.h>
#include <cstdint>

#define CIN   128
#define KOUT  256
#define HH    56
#define WW    56
#define NIMG  32
#define HWSZ  (HH*WW)            // 3136
#define PTOT  (NIMG*HWSZ)        // 100352
#define ETOT  1152
#define HPAD  58
#define WPAD  60
#define PLANE (HPAD*WPAD)        // 3480

#define TILE_M 128
#define TILE_N 256
#define TILE_K 16
#define NITER  (ETOT/TILE_K)     // 72
#define STAGES 4
#define SROWA  136               // padded floats per k-row of A tile
#define SROWB  264               // padded floats per k-row of B tile
#define AS_FLOATS (TILE_K*SROWA) // 2176
#define BS_FLOATS (TILE_K*SROWB) // 4224
#define STAGE_FLOATS (AS_FLOATS + BS_FLOATS)       // 6400
#define SMEM_BYTES (STAGES*STAGE_FLOATS*4)         // 102400

__device__ float XT[(size_t)NIMG*CIN*PLANE];   // padded NHW(C-major planes), tf32-rounded
__device__ float WTb[(size_t)ETOT*KOUT];       // [e=tap*128+c][k], tf32-rounded

__device__ __forceinline__ float rna_tf32(float v) {
    uint32_t u;
    asm("cvt.rna.tf32.f32 %0, %1;" : "=r"(u) : "f"(v));
    return __uint_as_float(u);
}
__device__ __forceinline__ void mma_tf32(float* d, const uint32_t* a, const uint32_t* b) {
    asm volatile(
        "mma.sync.aligned.m16n8k8.row.col.f32.tf32.tf32.f32 "
        "{%0,%1,%2,%3}, {%4,%5,%6,%7}, {%8,%9}, {%0,%1,%2,%3};"
        : "+f"(d[0]), "+f"(d[1]), "+f"(d[2]), "+f"(d[3])
        : "r"(a[0]), "r"(a[1]), "r"(a[2]), "r"(a[3]), "r"(b[0]), "r"(b[1]));
}
__device__ __forceinline__ void cp16(uint32_t dst, const void* src) {
    asm volatile("cp.async.cg.shared.global [%0], [%1], 16;" :: "r"(dst), "l"(src));
}
__device__ __forceinline__ void cp4(uint32_t dst, const void* src) {
    asm volatile("cp.async.ca.shared.global [%0], [%1], 4;" :: "r"(dst), "l"(src));
}

// ---------------- transforms ----------------
__global__ void transform_x(const float* __restrict__ x) {
    const int plane_id = blockIdx.x;              // n*CIN + c
    float* dst = XT + (size_t)plane_id * PLANE;
    const float* src = x + (size_t)plane_id * HWSZ;
    const int t = threadIdx.x;
    for (int i = t; i < PLANE; i += 256) dst[i] = 0.0f;
    __syncthreads();
    for (int i = t; i < HWSZ; i += 256) {
        const int h = i / WW;
        const int w = i - h * WW;
        dst[(h + 1) * WPAD + (w + 1)] = rna_tf32(src[i]);
    }
}

__global__ void transform_w(const float* __restrict__ k) {
    const int e  = blockIdx.x;     // 0..1151,  e = tap*128 + c
    const int kk = threadIdx.x;    // 0..255
    const int c   = e & 127;
    const int tap = e >> 7;
    WTb[(size_t)e * KOUT + kk] = rna_tf32(k[(size_t)kk * ETOT + c * 9 + tap]);
}

// ---------------- main kernel ----------------
__global__ void __launch_bounds__(256, 1)
conv_mma(const float* __restrict__ bias, float* __restrict__ out) {
    extern __shared__ float sm[];
    const int t    = threadIdx.x;
    const int warp = t >> 5;
    const int lane = t & 31;
    const int g    = lane >> 2;     // 0..7
    const int t4   = lane & 3;      // 0..3
    const int wm   = warp >> 2;     // 0..1  (M position, x64)
    const int wn   = warp & 3;      // 0..3  (N position, x64)
    const int p0   = blockIdx.x * TILE_N;
    const int m0   = blockIdx.y * TILE_M;

    // ---- per-thread B-load coords: thread owns pixel column pxn = t ----
    const int px  = p0 + t;
    const int img = px / HWSZ;
    const int hw  = px - img * HWSZ;
    const int oh  = hw / WW;
    const int ow  = hw - oh * WW;
    const float* xbase = XT + (size_t)img * CIN * PLANE + (size_t)oh * WPAD + ow;

    uint32_t sm_u32;
    { uint64_t tmp = __cvta_generic_to_shared(sm); sm_u32 = (uint32_t)tmp; }

    float acc[4][8][4];
    #pragma unroll
    for (int mi = 0; mi < 4; ++mi)
        #pragma unroll
        for (int nj = 0; nj < 8; ++nj)
            #pragma unroll
            for (int q = 0; q < 4; ++q) acc[mi][nj][q] = 0.0f;

    // ---- load issuer ----
    auto issue = [&](int it) {
        const int kb = it * TILE_K;
        const int stage = it & (STAGES - 1);
        const uint32_t asb = sm_u32 + stage * STAGE_FLOATS * 4;
        const uint32_t bsb = asb + AS_FLOATS * 4;
        // A tile: 16 rows x 128 floats, contiguous rows in WTb
        const float* Ag = WTb + (size_t)kb * KOUT + m0;
        #pragma unroll
        for (int q = 0; q < 2; ++q) {
            const int id = q * 256 + t;
            const int kk = id >> 5;
            const int mv = (id & 31) << 2;
            cp16(asb + (kk * SROWA + mv) * 4, Ag + (size_t)kk * KOUT + mv);
        }
        // B tile: 16 rows x 256 px, thread owns px=t for all 16 k-rows
        const int tap = kb >> 7;                       // constant within chunk
        const int r   = (tap >= 6) ? 2 : (tap >= 3 ? 1 : 0);
        const int s   = tap - r * 3;
        const float* Bg = xbase + (size_t)(kb & 127) * PLANE + r * WPAD + s;
        #pragma unroll
        for (int q = 0; q < 16; ++q)
            cp4(bsb + (q * SROWB + t) * 4, Bg + (size_t)q * PLANE);
    };

    issue(0); asm volatile("cp.async.commit_group;" ::: "memory");
    issue(1); asm volatile("cp.async.commit_group;" ::: "memory");
    issue(2); asm volatile("cp.async.commit_group;" ::: "memory");

    for (int it = 0; it < NITER; ++it) {
        asm volatile("cp.async.wait_group 2;" ::: "memory");
        __syncthreads();
        if (it + 3 < NITER) issue(it + 3);
        asm volatile("cp.async.commit_group;" ::: "memory");

        const int stage = it & (STAGES - 1);
        const float* As = sm + stage * STAGE_FLOATS;
        const float* Bs = As + AS_FLOATS;

        #pragma unroll
        for (int ks = 0; ks < 2; ++ks) {
            const float* Ak  = As + (ks * 8 + t4) * SROWA;
            const float* Ak4 = Ak + 4 * SROWA;
            const float* Bk  = Bs + (ks * 8 + t4) * SROWB;
            const float* Bk4 = Bk + 4 * SROWB;
            uint32_t a[4][4], b[8][2];
            #pragma unroll
            for (int mi = 0; mi < 4; ++mi) {
                const int m = wm * 64 + mi * 16 + g;
                a[mi][0] = *(const uint32_t*)(Ak  + m);
                a[mi][1] = *(const uint32_t*)(Ak  + m + 8);
                a[mi][2] = *(const uint32_t*)(Ak4 + m);
                a[mi][3] = *(const uint32_t*)(Ak4 + m + 8);
            }
            #pragma unroll
            for (int nj = 0; nj < 8; ++nj) {
                const int n = wn * 64 + nj * 8 + g;
                b[nj][0] = *(const uint32_t*)(Bk  + n);
                b[nj][1] = *(const uint32_t*)(Bk4 + n);
            }
            #pragma unroll
            for (int mi = 0; mi < 4; ++mi)
                #pragma unroll
                for (int nj = 0; nj < 8; ++nj)
                    mma_tf32(acc[mi][nj], a[mi], b[nj]);
        }
    }

    // ---- epilogue ----
    const float bv = bias[0];
    #pragma unroll
    for (int mi = 0; mi < 4; ++mi) {
        const int kch = m0 + wm * 64 + mi * 16 + g;
        #pragma unroll
        for (int nj = 0; nj < 8; ++nj) {
            const int p   = p0 + wn * 64 + nj * 8 + 2 * t4;
            const int im  = p / HWSZ;
            const int phw = p - im * HWSZ;
            float* o = out + ((size_t)im * KOUT + kch) * HWSZ + phw;
            float2 v0 = make_float2(acc[mi][nj][0] + bv, acc[mi][nj][1] + bv);
            float2 v1 = make_float2(acc[mi][nj][2] + bv, acc[mi][nj][3] + bv);
            *reinterpret_cast<float2*>(o) = v0;                    // row kch
            *reinterpret_cast<float2*>(o + 8 * HWSZ) = v1;         // row kch+8
        }
    }
}

// ---------------- host ----------------
extern "C" void kernel_launch(void* const* d_in, const int* in_sizes, int n_in,
                              void* d_out, int out_size) {
    const float* x    = (const float*)d_in[0];
    const float* K    = (const float*)d_in[1];
    const float* bias = (const float*)d_in[2];
    float* out        = (float*)d_out;

    cudaFuncSetAttribute(conv_mma, cudaFuncAttributeMaxDynamicSharedMemorySize, SMEM_BYTES);

    transform_x<<<NIMG * CIN, 256>>>(x);
    transform_w<<<ETOT, 256>>>(K);
    dim3 grid(PTOT / TILE_N, KOUT / TILE_M);   // (392, 2)
    conv_mma<<<grid, 256, SMEM_BYTES>>>(bias, out);
}

// round 5
// speedup vs baseline: 5.5298x; 1.5810x over previous
#include <cuda_runtime.h>
#include <cstdint>

#define CIN   128
#define KOUT  256
#define HH    56
#define WW    56
#define NIMG  32
#define HWSZ  (HH*WW)            // 3136
#define HPAD  58
#define WPAD  60
#define PLANE (HPAD*WPAD)        // 3480

#define TILE_M   128
#define ROWS_CTA 4
#define TILE_N   (ROWS_CTA*WW)   // 224
#define NGROUP   (HH/ROWS_CTA)   // 14
#define NCHUNK   16              // channel chunks
#define CPC      8               // channels per chunk

// smem layout (floats):
//  A stage: [tap(9)][mtile(8)][lane(32)][4]  = 9216 floats (36864 B)
//  B stage: [c(8)][row(6)][w(60)]            = 2880 floats (11520 B)
#define A_FLOATS 9216
#define B_FLOATS 2880
#define STAGE_FLOATS (A_FLOATS + B_FLOATS)   // 12096
#define SMEM_BYTES (2 * STAGE_FLOATS * 4)    // 96768

__device__ float XT[(size_t)NIMG*CIN*PLANE];      // padded planes, tf32-rounded
__device__ float WT2[(size_t)1152*KOUT];          // fragment-ordered weights

__device__ __forceinline__ float rna_tf32(float v) {
    uint32_t u;
    asm("cvt.rna.tf32.f32 %0, %1;" : "=r"(u) : "f"(v));
    return __uint_as_float(u);
}
__device__ __forceinline__ void mma_tf32(float* d, const uint32_t* a, const uint32_t* b) {
    asm volatile(
        "mma.sync.aligned.m16n8k8.row.col.f32.tf32.tf32.f32 "
        "{%0,%1,%2,%3}, {%4,%5,%6,%7}, {%8,%9}, {%0,%1,%2,%3};"
        : "+f"(d[0]), "+f"(d[1]), "+f"(d[2]), "+f"(d[3])
        : "r"(a[0]), "r"(a[1]), "r"(a[2]), "r"(a[3]), "r"(b[0]), "r"(b[1]));
}
__device__ __forceinline__ void cp16(uint32_t dst, const void* src) {
    asm volatile("cp.async.cg.shared.global [%0], [%1], 16;" :: "r"(dst), "l"(src));
}
__device__ __forceinline__ void lds128(uint32_t* r, uint32_t addr) {
    asm volatile("ld.shared.v4.b32 {%0,%1,%2,%3}, [%4];"
                 : "=r"(r[0]), "=r"(r[1]), "=r"(r[2]), "=r"(r[3]) : "r"(addr));
}

// ---------------- transforms ----------------
__global__ void transform_x(const float* __restrict__ x) {
    const int plane_id = blockIdx.x;              // n*CIN + c
    float* dst = XT + (size_t)plane_id * PLANE;
    const float* src = x + (size_t)plane_id * HWSZ;
    const int t = threadIdx.x;
    // zero only the halo border (rows 0,57 full; cols 0,57,58,59 of rows 1..56)
    if (t < WPAD) { dst[t] = 0.0f; dst[57 * WPAD + t] = 0.0f; }
    else if (t >= 64 && t < 64 + 224) {
        const int i = t - 64;
        const int row = (i >> 2) + 1;
        const int cid = i & 3;
        const int col = cid ? (56 + cid) : 0;
        dst[row * WPAD + col] = 0.0f;
    }
    for (int i = t; i < HWSZ; i += 256) {
        const int h = i / WW;
        const int w = i - h * WW;
        dst[(h + 1) * WPAD + (w + 1)] = rna_tf32(src[i]);
    }
}

// WT2[chunk][tap][mtile][lane][j]:
//   m = mtile*16 + g + (j&1)*8,  c = chunk*8 + t4 + (j>>1)*4,  (g=lane>>2, t4=lane&3)
//   value = rna_tf32(K[m][c][tap])   (OIHW)
__global__ void transform_w(const float* __restrict__ k) {
    const int idx = blockIdx.x * 256 + threadIdx.x;   // 294912 total
    const int chunk = idx / 18432;
    int r1 = idx - chunk * 18432;
    const int tap = r1 / 2048;  r1 -= tap * 2048;
    const int mt  = r1 >> 7;
    const int ln  = (r1 >> 2) & 31;
    const int j   = r1 & 3;
    const int g   = ln >> 2, t4 = ln & 3;
    const int m   = mt * 16 + g + (j & 1) * 8;
    const int c   = chunk * CPC + t4 + (j >> 1) * 4;
    WT2[idx] = rna_tf32(k[(size_t)(m * CIN + c) * 9 + tap]);
}

// ---------------- main kernel ----------------
__global__ void __launch_bounds__(256, 1)
conv_mma(const float* __restrict__ bias, float* __restrict__ out) {
    extern __shared__ float sm[];
    const int t    = threadIdx.x;
    const int warp = t >> 5;
    const int lane = t & 31;
    const int g    = lane >> 2;
    const int t4   = lane & 3;
    const int wm   = warp >> 2;     // 0..1
    const int wn   = warp & 3;      // 0..3 -> owns output row oh0+wn
    const int img  = blockIdx.x / NGROUP;
    const int grp  = blockIdx.x - img * NGROUP;
    const int oh0  = grp * ROWS_CTA;
    const int m0   = blockIdx.y * TILE_M;
    const int my0  = blockIdx.y * 8;   // mtile base in WT2

    uint32_t sm_u32;
    { uint64_t tmp = __cvta_generic_to_shared(sm); sm_u32 = (uint32_t)tmp; }

    float acc[4][7][4];
    #pragma unroll
    for (int mi = 0; mi < 4; ++mi)
        #pragma unroll
        for (int nj = 0; nj < 7; ++nj)
            #pragma unroll
            for (int q = 0; q < 4; ++q) acc[mi][nj][q] = 0.0f;

    const float* xg_base = XT + ((size_t)img * CIN) * PLANE + (size_t)oh0 * WPAD;

    auto issue = [&](int chunk) {
        const int stage = chunk & 1;
        const uint32_t ab = sm_u32 + stage * STAGE_FLOATS * 4;
        const uint32_t bb = ab + A_FLOATS * 4;
        // A: 2304 float4, 9 per thread; smem dst is linear in idx
        const float* ag = WT2 + (size_t)chunk * 18432;
        #pragma unroll
        for (int q = 0; q < 9; ++q) {
            const int idx  = q * 256 + t;
            const int tap  = idx >> 8;
            const int rem  = idx & 255;
            const int tile = rem >> 5;
            const int ln2  = rem & 31;
            cp16(ab + idx * 16,
                 ag + (size_t)tap * 2048 + (size_t)(my0 + tile) * 128 + ln2 * 4);
        }
        // B: 720 float4 (8c x 6 rows x 15 f4), <=3 per thread
        #pragma unroll
        for (int q = 0; q < 3; ++q) {
            const int idx = q * 256 + t;
            if (idx < 720) {
                const int c   = idx / 90;
                const int rem = idx - c * 90;
                const int row = rem / 15;
                const int f   = rem - row * 15;
                cp16(bb + ((c * 360 + row * 60) + f * 4) * 4,
                     xg_base + (size_t)(chunk * CPC + c) * PLANE + row * WPAD + f * 4);
            }
        }
    };

    issue(0);
    asm volatile("cp.async.commit_group;" ::: "memory");

    for (int chunk = 0; chunk < NCHUNK; ++chunk) {
        if (chunk + 1 < NCHUNK) {
            issue(chunk + 1);
            asm volatile("cp.async.commit_group;" ::: "memory");
            asm volatile("cp.async.wait_group 1;" ::: "memory");
        } else {
            asm volatile("cp.async.wait_group 0;" ::: "memory");
        }
        __syncthreads();

        const int stage = chunk & 1;
        const uint32_t a_base = sm_u32 + stage * STAGE_FLOATS * 4 + (wm * 4) * 512 + lane * 16;
        const float* Bs = sm + stage * STAGE_FLOATS + A_FLOATS;
        const float* Bw = Bs + t4 * 360 + wn * 60 + g;

        #pragma unroll
        for (int tap = 0; tap < 9; ++tap) {
            const int r = tap / 3;
            const int s = tap - r * 3;
            uint32_t a[4][4];
            #pragma unroll
            for (int mi = 0; mi < 4; ++mi)
                lds128(a[mi], a_base + tap * 4096 + mi * 512);
            uint32_t b[7][2];
            const int off = r * 60 + s;
            #pragma unroll
            for (int nj = 0; nj < 7; ++nj) {
                b[nj][0] = *(const uint32_t*)(Bw + off + nj * 8);
                b[nj][1] = *(const uint32_t*)(Bw + 1440 + off + nj * 8);
            }
            #pragma unroll
            for (int mi = 0; mi < 4; ++mi)
                #pragma unroll
                for (int nj = 0; nj < 7; ++nj)
                    mma_tf32(acc[mi][nj], a[mi], b[nj]);
        }
        __syncthreads();
    }

    // ---- epilogue ----
    const float bv = bias[0];
    const int orow = oh0 + wn;
    #pragma unroll
    for (int mi = 0; mi < 4; ++mi) {
        const int kch = m0 + wm * 64 + mi * 16 + g;
        float* o = out + ((size_t)img * KOUT + kch) * HWSZ + (size_t)orow * WW;
        #pragma unroll
        for (int nj = 0; nj < 7; ++nj) {
            const int ow = nj * 8 + 2 * t4;
            *reinterpret_cast<float2*>(o + ow) =
                make_float2(acc[mi][nj][0] + bv, acc[mi][nj][1] + bv);
            *reinterpret_cast<float2*>(o + 8 * HWSZ + ow) =
                make_float2(acc[mi][nj][2] + bv, acc[mi][nj][3] + bv);
        }
    }
}

// ---------------- host ----------------
extern "C" void kernel_launch(void* const* d_in, const int* in_sizes, int n_in,
                              void* d_out, int out_size) {
    const float* x    = (const float*)d_in[0];
    const float* K    = (const float*)d_in[1];
    const float* bias = (const float*)d_in[2];
    float* out        = (float*)d_out;

    cudaFuncSetAttribute(conv_mma, cudaFuncAttributeMaxDynamicSharedMemorySize, SMEM_BYTES);

    transform_x<<<NIMG * CIN, 256>>>(x);
    transform_w<<<1152, 256>>>(K);
    dim3 grid(NIMG * NGROUP, KOUT / TILE_M);   // (448, 2)
    conv_mma<<<grid, 256, SMEM_BYTES>>>(bias, out);
}

// round 6
// speedup vs baseline: 5.7057x; 1.0318x over previous
#include <cuda_runtime.h>
#include <cstdint>

#define CIN   128
#define KOUT  256
#define HH    56
#define WW    56
#define NIMG  32
#define HWSZ  (HH*WW)            // 3136
#define HPAD  58
#define WPAD  60
#define PLANE (HPAD*WPAD)        // 3480

#define TILE_M   64
#define ROWS_CTA 4
#define NGROUP   (HH/ROWS_CTA)   // 14
#define NCHUNK   16
#define CPC      8

// smem per stage (floats):
//  A: [tap(9)][mtile(4)][lane(32)][4] = 4608
//  B: [c(8)] blocks of (6 rows x 64 + 8 pad) = 392 each -> 3136
#define A_FLOATS 4608
#define B_FLOATS 3136
#define STAGE_FLOATS (A_FLOATS + B_FLOATS)   // 7744
#define STAGE_BYTES  (STAGE_FLOATS*4)        // 30976
#define SMEM_BYTES   (2*STAGE_BYTES)         // 61952

#define GUARD 16
__device__ __align__(64) float XTraw[GUARD + (size_t)NIMG*CIN*PLANE];
__device__ float WT2[(size_t)1152*KOUT];     // [chunk][tap][mtile16][lane][4]

__device__ __forceinline__ float rna_tf32(float v) {
    uint32_t u;
    asm("cvt.rna.tf32.f32 %0, %1;" : "=r"(u) : "f"(v));
    return __uint_as_float(u);
}
__device__ __forceinline__ void mma_tf32(float* d, const uint32_t* a, const uint32_t* b) {
    asm volatile(
        "mma.sync.aligned.m16n8k8.row.col.f32.tf32.tf32.f32 "
        "{%0,%1,%2,%3}, {%4,%5,%6,%7}, {%8,%9}, {%0,%1,%2,%3};"
        : "+f"(d[0]), "+f"(d[1]), "+f"(d[2]), "+f"(d[3])
        : "r"(a[0]), "r"(a[1]), "r"(a[2]), "r"(a[3]), "r"(b[0]), "r"(b[1]));
}
__device__ __forceinline__ void cp16(uint32_t dst, const void* src) {
    asm volatile("cp.async.cg.shared.global [%0], [%1], 16;" :: "r"(dst), "l"(src));
}
__device__ __forceinline__ void lds128(uint32_t* r, uint32_t addr) {
    asm volatile("ld.shared.v4.b32 {%0,%1,%2,%3}, [%4];"
                 : "=r"(r[0]), "=r"(r[1]), "=r"(r[2]), "=r"(r[3]) : "r"(addr));
}

// ---------------- combined transform ----------------
// blocks [0,4096): x planes.  blocks [4096,5248): weights.
__global__ void transform_all(const float* __restrict__ x, const float* __restrict__ k) {
    const int bid = blockIdx.x;
    const int t = threadIdx.x;
    if (bid < NIMG * CIN) {
        float* dst = XTraw + GUARD + (size_t)bid * PLANE;
        const float4* src = reinterpret_cast<const float4*>(x + (size_t)bid * HWSZ);
        if (bid == 0 && t < GUARD) XTraw[t] = 0.0f;
        const float4 z = make_float4(0.f, 0.f, 0.f, 0.f);
        // halo zeros: rows 0 & 57 (15 f4 each), right-pad col 56..59 rows 1..56
        if (t < 30) {
            const int row = (t < 15) ? 0 : 57;
            const int f = (t < 15) ? t : t - 15;
            *reinterpret_cast<float4*>(dst + row * WPAD + f * 4) = z;
        } else if (t < 86) {
            const int r = t - 30 + 1;
            *reinterpret_cast<float4*>(dst + r * WPAD + 56) = z;
        }
        // data: 784 f4 per plane, rows of 14 f4
        #pragma unroll
        for (int q = 0; q < 4; ++q) {
            const int idx = q * 256 + t;
            if (idx < 784) {
                const int h = idx / 14;
                const int f = idx - h * 14;
                float4 v = src[idx];
                v.x = rna_tf32(v.x); v.y = rna_tf32(v.y);
                v.z = rna_tf32(v.z); v.w = rna_tf32(v.w);
                *reinterpret_cast<float4*>(dst + (h + 1) * WPAD + f * 4) = v;
            }
        }
    } else {
        // weights -> fragment order (verified layout from round 5)
        const int idx = (bid - NIMG * CIN) * 256 + t;      // 294912 total
        const int chunk = idx / 18432;
        int r1 = idx - chunk * 18432;
        const int tap = r1 / 2048;  r1 -= tap * 2048;
        const int mt  = r1 >> 7;
        const int ln  = (r1 >> 2) & 31;
        const int j   = r1 & 3;
        const int g   = ln >> 2, t4 = ln & 3;
        const int m   = mt * 16 + g + (j & 1) * 8;
        const int c   = chunk * CPC + t4 + (j >> 1) * 4;
        WT2[idx] = rna_tf32(k[(size_t)(m * CIN + c) * 9 + tap]);
    }
}

// ---------------- main kernel ----------------
__global__ void __launch_bounds__(256, 2)
conv_mma(const float* __restrict__ bias, float* __restrict__ out) {
    extern __shared__ float sm[];
    const int t    = threadIdx.x;
    const int warp = t >> 5;
    const int lane = t & 31;
    const int g    = lane >> 2;
    const int t4   = lane & 3;
    const int wm   = warp >> 2;     // 0..1 : M halves of 32
    const int wn   = warp & 3;      // 0..3 : output row within group
    const int img  = blockIdx.x / NGROUP;
    const int grp  = blockIdx.x - img * NGROUP;
    const int oh0  = grp * ROWS_CTA;
    const int my0  = blockIdx.y * 4;                 // mtile base (16-row tiles)
    const int m0   = blockIdx.y * TILE_M;

    uint32_t sm_u32;
    { uint64_t tmp = __cvta_generic_to_shared(sm); sm_u32 = (uint32_t)tmp; }

    float acc[2][7][4];
    #pragma unroll
    for (int mi = 0; mi < 2; ++mi)
        #pragma unroll
        for (int nj = 0; nj < 7; ++nj)
            #pragma unroll
            for (int q = 0; q < 4; ++q) acc[mi][nj][q] = 0.0f;

    const float* XT = XTraw + GUARD;
    const float* xg_base = XT + ((size_t)img * CIN) * PLANE + (size_t)oh0 * WPAD;

    auto issue = [&](int chunk) {
        const int stage = chunk & 1;
        const uint32_t ab = sm_u32 + stage * STAGE_BYTES;
        const uint32_t bb = ab + A_FLOATS * 4;
        // A: 1152 f4 (this CTA's 4 mtiles x 9 taps)
        const float* ag = WT2 + (size_t)chunk * 18432;
        #pragma unroll
        for (int q = 0; q < 5; ++q) {
            const int idx = q * 256 + t;
            if (idx < 1152) {
                const int tap  = idx >> 7;
                const int rem  = idx & 127;
                const int tile = rem >> 5;
                const int ln2  = rem & 31;
                cp16(ab + idx * 16,
                     ag + (size_t)tap * 2048 + (size_t)(my0 + tile) * 128 + ln2 * 4);
            }
        }
        // B: 768 f4 = 8c x 6 rows x 16 f4 (cols -4..59), exactly 3/thread
        #pragma unroll
        for (int q = 0; q < 3; ++q) {
            const int idx = q * 256 + t;
            const int c   = idx / 96;
            const int rem = idx - c * 96;
            const int row = rem >> 4;
            const int f   = rem & 15;
            cp16(bb + (c * 392 + row * 64 + f * 4) * 4,
                 xg_base + (size_t)(chunk * CPC + c) * PLANE + row * WPAD + f * 4 - 4);
        }
    };

    issue(0);
    asm volatile("cp.async.commit_group;" ::: "memory");

    for (int chunk = 0; chunk < NCHUNK; ++chunk) {
        if (chunk + 1 < NCHUNK) {
            issue(chunk + 1);
            asm volatile("cp.async.commit_group;" ::: "memory");
            asm volatile("cp.async.wait_group 1;" ::: "memory");
        } else {
            asm volatile("cp.async.wait_group 0;" ::: "memory");
        }
        __syncthreads();

        const int stage = chunk & 1;
        const uint32_t a_base = sm_u32 + stage * STAGE_BYTES + (wm * 2) * 512 + lane * 16;
        const float* Bw = sm + stage * STAGE_FLOATS + A_FLOATS + t4 * 392 + wn * 64 + g;

        #pragma unroll
        for (int tap = 0; tap < 9; ++tap) {
            const int r = tap / 3;
            const int s = tap - r * 3;
            uint32_t a[2][4];
            #pragma unroll
            for (int mi = 0; mi < 2; ++mi)
                lds128(a[mi], a_base + tap * 2048 + mi * 512);
            uint32_t b[7][2];
            const int off = r * 64 + s + 3;
            #pragma unroll
            for (int nj = 0; nj < 7; ++nj) {
                b[nj][0] = *(const uint32_t*)(Bw + off + nj * 8);
                b[nj][1] = *(const uint32_t*)(Bw + 4 * 392 + off + nj * 8);
            }
            #pragma unroll
            for (int mi = 0; mi < 2; ++mi)
                #pragma unroll
                for (int nj = 0; nj < 7; ++nj)
                    mma_tf32(acc[mi][nj], a[mi], b[nj]);
        }
        __syncthreads();
    }

    // ---- epilogue ----
    const float bv = bias[0];
    const int orow = oh0 + wn;
    #pragma unroll
    for (int mi = 0; mi < 2; ++mi) {
        const int kch = m0 + wm * 32 + mi * 16 + g;
        float* o = out + ((size_t)img * KOUT + kch) * HWSZ + (size_t)orow * WW;
        #pragma unroll
        for (int nj = 0; nj < 7; ++nj) {
            const int ow = nj * 8 + 2 * t4;
            *reinterpret_cast<float2*>(o + ow) =
                make_float2(acc[mi][nj][0] + bv, acc[mi][nj][1] + bv);
            *reinterpret_cast<float2*>(o + 8 * HWSZ + ow) =
                make_float2(acc[mi][nj][2] + bv, acc[mi][nj][3] + bv);
        }
    }
}

// ---------------- host ----------------
extern "C" void kernel_launch(void* const* d_in, const int* in_sizes, int n_in,
                              void* d_out, int out_size) {
    const float* x    = (const float*)d_in[0];
    const float* K    = (const float*)d_in[1];
    const float* bias = (const float*)d_in[2];
    float* out        = (float*)d_out;

    cudaFuncSetAttribute(conv_mma, cudaFuncAttributeMaxDynamicSharedMemorySize, SMEM_BYTES);

    transform_all<<<NIMG * CIN + 1152, 256>>>(x, K);
    dim3 grid(NIMG * NGROUP, KOUT / TILE_M);   // (448, 4) = 1792 CTAs
    conv_mma<<<grid, 256, SMEM_BYTES>>>(bias, out);
}

// round 7
// speedup vs baseline: 6.0306x; 1.0569x over previous
#include <cuda_runtime.h>
#include <cstdint>

#define CIN   128
#define KOUT  256
#define HH    56
#define WW    56
#define NIMG  32
#define HWSZ  (HH*WW)            // 3136
#define HPAD  58
#define WPAD  60
#define PLANE (HPAD*WPAD)        // 3480

#define TILE_M   64
#define ROWS_CTA 4
#define NGROUP   (HH/ROWS_CTA)   // 14
#define NCHUNK   16
#define CPC      8

// smem per stage (floats):
//  A: [tap(9)][mtile(2x32rows->4x16)][lane(32)][4] = 4608
//  B: [c(8)] blocks of (6 rows x 64 + 8 pad) = 392 each -> 3136
#define A_FLOATS 4608
#define B_FLOATS 3136
#define STAGE_FLOATS (A_FLOATS + B_FLOATS)   // 7744
#define STAGE_BYTES  (STAGE_FLOATS*4)        // 30976
#define STAGES 3
#define SMEM_BYTES   (STAGES*STAGE_BYTES)    // 92928

#define GUARD 16
__device__ __align__(64) float XTraw[GUARD + (size_t)NIMG*CIN*PLANE];
__device__ float WT2[(size_t)1152*KOUT];     // [chunk][tap][mtile16][lane][4]

__device__ __forceinline__ float rna_tf32(float v) {
    uint32_t u;
    asm("cvt.rna.tf32.f32 %0, %1;" : "=r"(u) : "f"(v));
    return __uint_as_float(u);
}
__device__ __forceinline__ void mma_tf32(float* d, const uint32_t* a, const uint32_t* b) {
    asm volatile(
        "mma.sync.aligned.m16n8k8.row.col.f32.tf32.tf32.f32 "
        "{%0,%1,%2,%3}, {%4,%5,%6,%7}, {%8,%9}, {%0,%1,%2,%3};"
        : "+f"(d[0]), "+f"(d[1]), "+f"(d[2]), "+f"(d[3])
        : "r"(a[0]), "r"(a[1]), "r"(a[2]), "r"(a[3]), "r"(b[0]), "r"(b[1]));
}
__device__ __forceinline__ void cp16(uint32_t dst, const void* src) {
    asm volatile("cp.async.cg.shared.global [%0], [%1], 16;" :: "r"(dst), "l"(src));
}
__device__ __forceinline__ void lds128(uint32_t* r, uint32_t addr) {
    asm volatile("ld.shared.v4.b32 {%0,%1,%2,%3}, [%4];"
                 : "=r"(r[0]), "=r"(r[1]), "=r"(r[2]), "=r"(r[3]) : "r"(addr));
}

// ---------------- combined transform ----------------
__global__ void transform_all(const float* __restrict__ x, const float* __restrict__ k) {
    const int bid = blockIdx.x;
    const int t = threadIdx.x;
    if (bid < NIMG * CIN) {
        float* dst = XTraw + GUARD + (size_t)bid * PLANE;
        const float4* src = reinterpret_cast<const float4*>(x + (size_t)bid * HWSZ);
        if (bid == 0 && t < GUARD) XTraw[t] = 0.0f;
        const float4 z = make_float4(0.f, 0.f, 0.f, 0.f);
        if (t < 30) {
            const int row = (t < 15) ? 0 : 57;
            const int f = (t < 15) ? t : t - 15;
            *reinterpret_cast<float4*>(dst + row * WPAD + f * 4) = z;
        } else if (t < 86) {
            const int r = t - 30 + 1;
            *reinterpret_cast<float4*>(dst + r * WPAD + 56) = z;
        }
        #pragma unroll
        for (int q = 0; q < 4; ++q) {
            const int idx = q * 256 + t;
            if (idx < 784) {
                const int h = idx / 14;
                const int f = idx - h * 14;
                float4 v = src[idx];
                v.x = rna_tf32(v.x); v.y = rna_tf32(v.y);
                v.z = rna_tf32(v.z); v.w = rna_tf32(v.w);
                *reinterpret_cast<float4*>(dst + (h + 1) * WPAD + f * 4) = v;
            }
        }
    } else {
        const int idx = (bid - NIMG * CIN) * 256 + t;      // 294912 total
        const int chunk = idx / 18432;
        int r1 = idx - chunk * 18432;
        const int tap = r1 / 2048;  r1 -= tap * 2048;
        const int mt  = r1 >> 7;
        const int ln  = (r1 >> 2) & 31;
        const int j   = r1 & 3;
        const int g   = ln >> 2, t4 = ln & 3;
        const int m   = mt * 16 + g + (j & 1) * 8;
        const int c   = chunk * CPC + t4 + (j >> 1) * 4;
        WT2[idx] = rna_tf32(k[(size_t)(m * CIN + c) * 9 + tap]);
    }
}

// ---------------- main kernel ----------------
__global__ void __launch_bounds__(256, 2)
conv_mma(const float* __restrict__ bias, float* __restrict__ out) {
    extern __shared__ float sm[];
    const int t    = threadIdx.x;
    const int warp = t >> 5;
    const int lane = t & 31;
    const int g    = lane >> 2;
    const int t4   = lane & 3;
    const int wm   = warp >> 2;     // 0..1 : M halves of 32
    const int wn   = warp & 3;      // 0..3 : output row within group
    const int img  = blockIdx.y / NGROUP;
    const int grp  = blockIdx.y - img * NGROUP;
    const int oh0  = grp * ROWS_CTA;
    const int my0  = blockIdx.x * 4;                 // mtile base (16-row tiles)
    const int m0   = blockIdx.x * TILE_M;

    uint32_t sm_u32;
    { uint64_t tmp = __cvta_generic_to_shared(sm); sm_u32 = (uint32_t)tmp; }

    float acc[2][7][4];
    #pragma unroll
    for (int mi = 0; mi < 2; ++mi)
        #pragma unroll
        for (int nj = 0; nj < 7; ++nj)
            #pragma unroll
            for (int q = 0; q < 4; ++q) acc[mi][nj][q] = 0.0f;

    const float* XT = XTraw + GUARD;
    const float* xg_base = XT + ((size_t)img * CIN) * PLANE + (size_t)oh0 * WPAD;

    auto issue = [&](int chunk, int stage) {
        const uint32_t ab = sm_u32 + stage * STAGE_BYTES;
        const uint32_t bb = ab + A_FLOATS * 4;
        const float* ag = WT2 + (size_t)chunk * 18432;
        #pragma unroll
        for (int q = 0; q < 5; ++q) {
            const int idx = q * 256 + t;
            if (idx < 1152) {
                const int tap  = idx >> 7;
                const int rem  = idx & 127;
                const int tile = rem >> 5;
                const int ln2  = rem & 31;
                cp16(ab + idx * 16,
                     ag + (size_t)tap * 2048 + (size_t)(my0 + tile) * 128 + ln2 * 4);
            }
        }
        #pragma unroll
        for (int q = 0; q < 3; ++q) {
            const int idx = q * 256 + t;
            const int c   = idx / 96;
            const int rem = idx - c * 96;
            const int row = rem >> 4;
            const int f   = rem & 15;
            cp16(bb + (c * 392 + row * 64 + f * 4) * 4,
                 xg_base + (size_t)(chunk * CPC + c) * PLANE + row * WPAD + f * 4 - 4);
        }
    };

    issue(0, 0);
    asm volatile("cp.async.commit_group;" ::: "memory");
    issue(1, 1);
    asm volatile("cp.async.commit_group;" ::: "memory");

    int stage = 0;          // stage of current chunk
    int stage2 = 2;         // stage for chunk+2
    for (int chunk = 0; chunk < NCHUNK; ++chunk) {
        asm volatile("cp.async.wait_group 1;" ::: "memory");
        __syncthreads();

        const uint32_t a_base = sm_u32 + stage * STAGE_BYTES + (wm * 2) * 512 + lane * 16;
        const float* Bw = sm + stage * STAGE_FLOATS + A_FLOATS + t4 * 392 + wn * 64 + g;

        // preload tap-0 B fragments
        uint32_t bc[7][2];
        #pragma unroll
        for (int nj = 0; nj < 7; ++nj) {
            bc[nj][0] = *(const uint32_t*)(Bw + 3 + nj * 8);
            bc[nj][1] = *(const uint32_t*)(Bw + 1568 + 3 + nj * 8);
        }

        #pragma unroll
        for (int tap = 0; tap < 9; ++tap) {
            uint32_t a[2][4];
            lds128(a[0], a_base + tap * 2048);
            lds128(a[1], a_base + tap * 2048 + 512);

            uint32_t bn[7][2];
            if (tap < 8) {
                const int tp = tap + 1;
                const int r2 = tp / 3;
                const int s2 = tp - r2 * 3;
                const int off2 = r2 * 64 + s2 + 3;
                #pragma unroll
                for (int nj = 0; nj < 7; ++nj) {
                    bn[nj][0] = *(const uint32_t*)(Bw + off2 + nj * 8);
                    bn[nj][1] = *(const uint32_t*)(Bw + 1568 + off2 + nj * 8);
                }
            }

            #pragma unroll
            for (int mi = 0; mi < 2; ++mi)
                #pragma unroll
                for (int nj = 0; nj < 7; ++nj)
                    mma_tf32(acc[mi][nj], a[mi], bc[nj]);

            if (tap < 8) {
                #pragma unroll
                for (int nj = 0; nj < 7; ++nj) {
                    bc[nj][0] = bn[nj][0];
                    bc[nj][1] = bn[nj][1];
                }
            }
        }

        // issue chunk+2 into the stage last read at chunk-1 (safe: sync above
        // guarantees all warps finished chunk-1)
        if (chunk + 2 < NCHUNK) issue(chunk + 2, stage2);
        asm volatile("cp.async.commit_group;" ::: "memory");

        stage  = (stage  == 2) ? 0 : stage  + 1;
        stage2 = (stage2 == 2) ? 0 : stage2 + 1;
    }

    // ---- epilogue ----
    const float bv = bias[0];
    const int orow = oh0 + wn;
    #pragma unroll
    for (int mi = 0; mi < 2; ++mi) {
        const int kch = m0 + wm * 32 + mi * 16 + g;
        float* o = out + ((size_t)img * KOUT + kch) * HWSZ + (size_t)orow * WW;
        #pragma unroll
        for (int nj = 0; nj < 7; ++nj) {
            const int ow = nj * 8 + 2 * t4;
            *reinterpret_cast<float2*>(o + ow) =
                make_float2(acc[mi][nj][0] + bv, acc[mi][nj][1] + bv);
            *reinterpret_cast<float2*>(o + 8 * HWSZ + ow) =
                make_float2(acc[mi][nj][2] + bv, acc[mi][nj][3] + bv);
        }
    }
}

// ---------------- host ----------------
extern "C" void kernel_launch(void* const* d_in, const int* in_sizes, int n_in,
                              void* d_out, int out_size) {
    const float* x    = (const float*)d_in[0];
    const float* K    = (const float*)d_in[1];
    const float* bias = (const float*)d_in[2];
    float* out        = (float*)d_out;

    cudaFuncSetAttribute(conv_mma, cudaFuncAttributeMaxDynamicSharedMemorySize, SMEM_BYTES);

    transform_all<<<NIMG * CIN + 1152, 256>>>(x, K);
    dim3 grid(KOUT / TILE_M, NIMG * NGROUP);   // (4, 448) — mtiles fastest
    conv_mma<<<grid, 256, SMEM_BYTES>>>(bias, out);
}